// round 15
// baseline (speedup 1.0000x reference)
#include <cuda_runtime.h>
#include <cuda_fp16.h>
#include <cstdint>

#define NINST 64
#define HDIM 100
#define WDIM 152
#define HW 15200
#define NB 32
#define NKP 17
#define ATTN_LEN 2737
#define KDIM 2304
#define KSPLIT 8
#define KCHUNK (KDIM / KSPLIT)   // 288
#define IPB 4                    // instances per mlp CTA
#define IGY (NINST / IPB)        // 16
#define GX 60                    // ceil(HW / 256)
#define NQ16 22                  // uint4 B-fragment entries per instance per lane
#define BFRAG16 (NQ16 * 32)      // 704 uint4 per instance
#define NT16 950                 // HW / 16 (m16 tiles)

typedef unsigned long long ull;

__device__ float g_attns[NINST * ATTN_LEN];
__device__ float g_part[KSPLIT * NINST * ATTN_LEN];
__device__ uint4 g_bfrag[NINST * BFRAG16];
__device__ uint2 g_bbf[NT16 * 256];   // layer-1 A frags: [tile16][e(8)][lane(32)] (hi,lo)

// ---------------- packed f32x2 helpers (gemm) ----------------
__device__ __forceinline__ ull pack2(float x, float y) {
    ull r; asm("mov.b64 %0, {%1, %2};" : "=l"(r) : "f"(x), "f"(y)); return r;
}
__device__ __forceinline__ ull ffma2(ull a, ull b, ull c) {
    ull d; asm("fma.rn.f32x2 %0, %1, %2, %3;" : "=l"(d) : "l"(a), "l"(b), "l"(c)); return d;
}
__device__ __forceinline__ float2 unpack2(ull v) {
    float2 r; asm("mov.b64 {%0, %1}, %2;" : "=f"(r.x), "=f"(r.y) : "l"(v)); return r;
}

// ---------------- fp16 split helpers ----------------
__device__ __forceinline__ void h2_split(float x0, float x1, uint32_t& hi, uint32_t& lo) {
    unsigned short s0 = __half_as_ushort(__float2half_rn(x0));
    unsigned short s1 = __half_as_ushort(__float2half_rn(x1));
    float l0 = x0 - __half2float(__ushort_as_half(s0));
    float l1 = x1 - __half2float(__ushort_as_half(s1));
    unsigned short t0 = __half_as_ushort(__float2half_rn(l0));
    unsigned short t1 = __half_as_ushort(__float2half_rn(l1));
    hi = (uint32_t)s0 | ((uint32_t)s1 << 16);
    lo = (uint32_t)t0 | ((uint32_t)t1 << 16);
}
__device__ __forceinline__ void mma_f16(float* c, const uint32_t* a, uint32_t b0, uint32_t b1) {
    asm volatile(
        "mma.sync.aligned.m16n8k16.row.col.f32.f16.f16.f32 "
        "{%0,%1,%2,%3}, {%4,%5,%6,%7}, {%8,%9}, {%0,%1,%2,%3};"
        : "+f"(c[0]), "+f"(c[1]), "+f"(c[2]), "+f"(c[3])
        : "r"(a[0]), "r"(a[1]), "r"(a[2]), "r"(a[3]), "r"(b0), "r"(b1));
}

// ---------------------------------------------------------------------------
// Kernel A1: split-K partial GEMM (fp32, exact — R11 version).
// ---------------------------------------------------------------------------
__global__ __launch_bounds__(128) void gemm_partial(const float* __restrict__ A,
                                                    const float* __restrict__ Wm) {
    __shared__ __align__(16) float As[32][64];
    __shared__ __align__(16) float Ws[32][16];
    int tid = threadIdx.x;
    int jblk = blockIdx.x * 16;
    int kbase = blockIdx.y * KCHUNK;

    int an = tid >> 1;
    int ak = (tid & 1) * 16;
    int wj = tid >> 3;
    int wk = (tid & 7) * 4;
    int n0 = (tid & 15) * 4;
    int j0 = (tid >> 4) * 2;

    ull acc2[2][2];
    acc2[0][0] = acc2[0][1] = acc2[1][0] = acc2[1][1] = 0ULL;

    for (int k0 = kbase; k0 < kbase + KCHUNK; k0 += 32) {
        __syncthreads();
        const float4* ap = (const float4*)(A + (size_t)an * KDIM + k0 + ak);
#pragma unroll
        for (int v = 0; v < 4; v++) {
            float4 t = ap[v];
            As[ak + v * 4 + 0][an] = t.x;
            As[ak + v * 4 + 1][an] = t.y;
            As[ak + v * 4 + 2][an] = t.z;
            As[ak + v * 4 + 3][an] = t.w;
        }
        {
            int j = jblk + wj;
            float4 t = make_float4(0.f, 0.f, 0.f, 0.f);
            if (j < ATTN_LEN)
                t = *(const float4*)(Wm + (size_t)j * KDIM + k0 + wk);
            Ws[wk + 0][wj] = t.x;
            Ws[wk + 1][wj] = t.y;
            Ws[wk + 2][wj] = t.z;
            Ws[wk + 3][wj] = t.w;
        }
        __syncthreads();
#pragma unroll
        for (int kk = 0; kk < 32; kk++) {
            ulonglong2 a2 = *(const ulonglong2*)&As[kk][n0];
            float2 wf = *(const float2*)&Ws[kk][j0];
            ull wx = pack2(wf.x, wf.x);
            ull wy = pack2(wf.y, wf.y);
            acc2[0][0] = ffma2(a2.x, wx, acc2[0][0]);
            acc2[0][1] = ffma2(a2.x, wy, acc2[0][1]);
            acc2[1][0] = ffma2(a2.y, wx, acc2[1][0]);
            acc2[1][1] = ffma2(a2.y, wy, acc2[1][1]);
        }
    }
    float* outp = g_part + (size_t)blockIdx.y * NINST * ATTN_LEN;
#pragma unroll
    for (int p = 0; p < 2; p++) {
#pragma unroll
        for (int dj = 0; dj < 2; dj++) {
            int j = jblk + j0 + dj;
            if (j < ATTN_LEN) {
                float2 u = unpack2(acc2[p][dj]);
                outp[(size_t)(n0 + 2 * p)     * ATTN_LEN + j] = u.x;
                outp[(size_t)(n0 + 2 * p + 1) * ATTN_LEN + j] = u.y;
            }
        }
    }
}

// ---------------------------------------------------------------------------
// Kernel A2+A3 fused: per-instance split-K reduce + bias, then build fp16
// B fragments from the freshly written row (block-local: write -> sync ->
// read within one block on one SM is coherent).
// ---------------------------------------------------------------------------
__global__ __launch_bounds__(512) void reduce_and_bfrag(const float* __restrict__ bias) {
    int n = blockIdx.x;
    int tid = threadIdx.x;
    float* row = g_attns + (size_t)n * ATTN_LEN;

    for (int j = tid; j < ATTN_LEN; j += 512) {
        size_t idx = (size_t)n * ATTN_LEN + j;
        float s = 0.f;
#pragma unroll
        for (int p = 0; p < KSPLIT; p++) s += g_part[(size_t)p * NINST * ATTN_LEN + idx];
        row[j] = s + bias[j];
    }
    __syncthreads();

    uint4* dst = g_bfrag + (size_t)n * BFRAG16;
    for (int e = tid; e < BFRAG16; e += 512) {
        int lane = e & 31;
        int q = e >> 5;
        int layer, qq;
        if (q < 8)       { layer = 0; qq = q; }
        else if (q < 16) { layer = 1; qq = q - 8; }
        else             { layer = 2; qq = q - 16; }
        int nt = qq >> 1, kt = qq & 1;
        int g = lane >> 2, tig = lane & 3;
        int o = nt * 8 + g;
        int c0 = kt * 16 + 2 * tig;

        float x0 = 0.f, x1 = 0.f, x2 = 0.f, x3 = 0.f;
        if (layer == 0) {
            x0 = row[o * 34 + c0 + 2];  x1 = row[o * 34 + c0 + 3];
            x2 = row[o * 34 + c0 + 10]; x3 = row[o * 34 + c0 + 11];
        } else if (layer == 1) {
            x0 = row[1120 + o * 32 + c0];     x1 = row[1120 + o * 32 + c0 + 1];
            x2 = row[1120 + o * 32 + c0 + 8]; x3 = row[1120 + o * 32 + c0 + 9];
        } else if (o < NKP) {
            x0 = row[2176 + o * 32 + c0];     x1 = row[2176 + o * 32 + c0 + 1];
            x2 = row[2176 + o * 32 + c0 + 8]; x3 = row[2176 + o * 32 + c0 + 9];
        }
        uint32_t h0, l0, h1, l1;
        h2_split(x0, x1, h0, l0);
        h2_split(x2, x3, h1, l1);
        dst[e] = make_uint4(h0, h1, l0, l1);
    }
}

// ---------------------------------------------------------------------------
// Kernel A4: pre-build layer-1 A fragments in fragment-major layout.
// ---------------------------------------------------------------------------
__global__ __launch_bounds__(256) void prep_bases_frag(const float* __restrict__ bases_full) {
    int tile = blockIdx.x;
    int tid = threadIdx.x;
    int lane = tid & 31, e = tid >> 5;
    int g = lane >> 2, tig = lane & 3;
    int kt = e >> 2, r = e & 3;
    int px = tile * 16 + g + ((r & 1) << 3);
    int p = kt * 8 + ((r >> 1) << 2) + tig;
    float x0 = bases_full[(size_t)(2 * p)     * HW + px];
    float x1 = bases_full[(size_t)(2 * p + 1) * HW + px];
    uint32_t hi, lo;
    h2_split(x0, x1, hi, lo);
    g_bbf[tile * 256 + e * 32 + lane] = make_uint2(hi, lo);
}

// ---------------------------------------------------------------------------
// Kernel B: MLP via mma.sync m16n8k16 fp16 (2-way split, 3 passes),
// register-resident hand-off, restructured mt-OUTER: one m16 tile through
// all 3 layers at a time -> ah[8]/al[8]+cc[4][4] live set (~70 regs),
// 3 CTAs/SM. B frags re-ldg'd per mt but L1-hot (shared by 8 warps).
// ---------------------------------------------------------------------------
__global__ __launch_bounds__(256, 3) void mlp_mma16(const float* __restrict__ locations,
                                                    const float* __restrict__ sizes,
                                                    const int* __restrict__ fpn_levels,
                                                    float* __restrict__ out) {
    int tid = threadIdx.x;
    int warp = tid >> 5;
    int lane = tid & 31;
    int g = lane >> 2, tig = lane & 3;

    int pxb = blockIdx.x * 256 + warp * 32;
    if (pxb >= HW) return;
    int t0 = pxb >> 4;

    float gxv[4], gyv[4];
#pragma unroll
    for (int r = 0; r < 4; r++) {
        int p = pxb + (r >> 1) * 16 + g + (r & 1) * 8;
        gxv[r] = (float)(p % WDIM) * 8.f + 4.f;
        gyv[r] = (float)(p / WDIM) * 8.f + 4.f;
    }

    int nbase = blockIdx.y * IPB;
    for (int ii = 0; ii < IPB; ii++) {
        int n = nbase + ii;
        const uint4* bf = g_bfrag + (size_t)n * BFRAG16;
        const float* row = g_attns + (size_t)n * ATTN_LEN;
        float invr = 1.f / sizes[fpn_levels[n]];
        float lx = locations[2 * n], ly = locations[2 * n + 1];
        float* ob = out + (size_t)n * NKP * HW;

#pragma unroll
        for (int mt = 0; mt < 2; mt++) {
            uint32_t ah[8], al[8];
            float cc[4][4];

            // ---------- layer 1: A from fragment-major global (coalesced) ----------
#pragma unroll
            for (int e = 0; e < 8; e++) {
                uint2 u = __ldg(&g_bbf[(t0 + mt) * 256 + e * 32 + lane]);
                ah[e] = u.x;
                al[e] = u.y;
            }
#pragma unroll
            for (int nt = 0; nt < 4; nt++) {
#pragma unroll
                for (int j = 0; j < 4; j++) cc[nt][j] = 0.f;
#pragma unroll
                for (int kt = 0; kt < 2; kt++) {
                    uint4 f = __ldg(bf + (nt * 2 + kt) * 32 + lane);
                    mma_f16(cc[nt], &ah[kt * 4], f.x, f.y);
                    mma_f16(cc[nt], &ah[kt * 4], f.z, f.w);
                    mma_f16(cc[nt], &al[kt * 4], f.x, f.y);
                }
            }
            // epilogue L1: offsets + bias + relu, rebuild A frags in registers
            {
                float ox0 = (lx - gxv[2 * mt]) * invr,     oy0 = (ly - gyv[2 * mt]) * invr;
                float ox1 = (lx - gxv[2 * mt + 1]) * invr, oy1 = (ly - gyv[2 * mt + 1]) * invr;
#pragma unroll
                for (int kt = 0; kt < 2; kt++)
#pragma unroll
                    for (int h = 0; h < 2; h++) {
                        int nt = 2 * kt + h;
                        int o0 = nt * 8 + 2 * tig, o1 = o0 + 1;
                        float wx0 = row[o0 * 34], wy0 = row[o0 * 34 + 1], bb0 = row[1088 + o0];
                        float wx1 = row[o1 * 34], wy1 = row[o1 * 34 + 1], bb1 = row[1088 + o1];
                        float v00 = fmaxf(cc[nt][0] + wx0 * ox0 + wy0 * oy0 + bb0, 0.f);
                        float v01 = fmaxf(cc[nt][1] + wx1 * ox0 + wy1 * oy0 + bb1, 0.f);
                        float v10 = fmaxf(cc[nt][2] + wx0 * ox1 + wy0 * oy1 + bb0, 0.f);
                        float v11 = fmaxf(cc[nt][3] + wx1 * ox1 + wy1 * oy1 + bb1, 0.f);
                        h2_split(v00, v01, ah[kt * 4 + 2 * h + 0], al[kt * 4 + 2 * h + 0]);
                        h2_split(v10, v11, ah[kt * 4 + 2 * h + 1], al[kt * 4 + 2 * h + 1]);
                    }
            }

            // ---------- layer 2 ----------
#pragma unroll
            for (int nt = 0; nt < 4; nt++) {
#pragma unroll
                for (int j = 0; j < 4; j++) cc[nt][j] = 0.f;
            }
#pragma unroll
            for (int nt = 0; nt < 4; nt++)
#pragma unroll
                for (int kt = 0; kt < 2; kt++) {
                    uint4 f = __ldg(bf + (8 + nt * 2 + kt) * 32 + lane);
                    mma_f16(cc[nt], &ah[kt * 4], f.x, f.y);
                    mma_f16(cc[nt], &ah[kt * 4], f.z, f.w);
                    mma_f16(cc[nt], &al[kt * 4], f.x, f.y);
                }
#pragma unroll
            for (int kt = 0; kt < 2; kt++)
#pragma unroll
                for (int h = 0; h < 2; h++) {
                    int nt = 2 * kt + h;
                    int o0 = nt * 8 + 2 * tig, o1 = o0 + 1;
                    float bb0 = row[2144 + o0], bb1 = row[2144 + o1];
                    float v00 = fmaxf(cc[nt][0] + bb0, 0.f);
                    float v01 = fmaxf(cc[nt][1] + bb1, 0.f);
                    float v10 = fmaxf(cc[nt][2] + bb0, 0.f);
                    float v11 = fmaxf(cc[nt][3] + bb1, 0.f);
                    h2_split(v00, v01, ah[kt * 4 + 2 * h + 0], al[kt * 4 + 2 * h + 0]);
                    h2_split(v10, v11, ah[kt * 4 + 2 * h + 1], al[kt * 4 + 2 * h + 1]);
                }

            // ---------- layer 3 (nt 0..2, write o < 17) ----------
#pragma unroll
            for (int nt = 0; nt < 3; nt++) {
#pragma unroll
                for (int j = 0; j < 4; j++) cc[nt][j] = 0.f;
#pragma unroll
                for (int kt = 0; kt < 2; kt++) {
                    uint4 f = __ldg(bf + (16 + nt * 2 + kt) * 32 + lane);
                    mma_f16(cc[nt], &ah[kt * 4], f.x, f.y);
                    mma_f16(cc[nt], &ah[kt * 4], f.z, f.w);
                    mma_f16(cc[nt], &al[kt * 4], f.x, f.y);
                }
            }
            {
                int px0 = pxb + 16 * mt + g, px1 = px0 + 8;
#pragma unroll
                for (int nt = 0; nt < 3; nt++) {
                    int o0 = nt * 8 + 2 * tig, o1 = o0 + 1;
                    if (o0 < NKP) {
                        float bb0 = row[2720 + o0];
                        ob[(size_t)o0 * HW + px0] = cc[nt][0] + bb0;
                        ob[(size_t)o0 * HW + px1] = cc[nt][2] + bb0;
                    }
                    if (o1 < NKP) {
                        float bb1 = row[2720 + o1];
                        ob[(size_t)o1 * HW + px0] = cc[nt][1] + bb1;
                        ob[(size_t)o1 * HW + px1] = cc[nt][3] + bb1;
                    }
                }
            }
        }
    }
}

// ---------------------------------------------------------------------------
// Kernel C: per (n, kp) argmax over HW, 4 independent accumulator chains,
// first-index tie-break preserved.
// ---------------------------------------------------------------------------
__global__ __launch_bounds__(256) void argmax_kernel(float* __restrict__ out,
                                                     const float* __restrict__ bases_full) {
    int pair = blockIdx.x;
    int k = pair % NKP;
    const float4* lg = (const float4*)(out + (size_t)pair * HW);
    int tid = threadIdx.x;

    float bv0 = -3.4e38f, bv1 = -3.4e38f, bv2 = -3.4e38f, bv3 = -3.4e38f;
    int bi0 = 0, bi1 = 1, bi2 = 2, bi3 = 3;
    for (int q = tid; q < HW / 4; q += 256) {
        float4 v = lg[q];
        int i0 = q * 4;
        if (v.x > bv0) { bv0 = v.x; bi0 = i0; }
        if (v.y > bv1) { bv1 = v.y; bi1 = i0 + 1; }
        if (v.z > bv2) { bv2 = v.z; bi2 = i0 + 2; }
        if (v.w > bv3) { bv3 = v.w; bi3 = i0 + 3; }
    }
    float best = bv0; int bi = bi0;
    if (bv1 > best || (bv1 == best && bi1 < bi)) { best = bv1; bi = bi1; }
    if (bv2 > best || (bv2 == best && bi2 < bi)) { best = bv2; bi = bi2; }
    if (bv3 > best || (bv3 == best && bi3 < bi)) { best = bv3; bi = bi3; }

    __shared__ float sv[256];
    __shared__ int si[256];
    sv[tid] = best;
    si[tid] = bi;
    __syncthreads();
#pragma unroll
    for (int s = 128; s > 0; s >>= 1) {
        if (tid < s) {
            float ov = sv[tid + s]; int oi = si[tid + s];
            if (ov > sv[tid] || (ov == sv[tid] && oi < si[tid])) {
                sv[tid] = ov; si[tid] = oi;
            }
        }
        __syncthreads();
    }
    if (tid == 0) {
        int i = si[0];
        float gx = (float)(i % WDIM) * 8.f + 4.f;
        float gy = (float)(i / WDIM) * 8.f + 4.f;
        float* kp = out + (size_t)NINST * NKP * HW + (size_t)pair * 2;
        kp[0] = bases_full[(size_t)(NB + 2 * k)     * HW + i] + gx;
        kp[1] = bases_full[(size_t)(NB + 2 * k + 1) * HW + i] + gy;
    }
}

// ---------------------------------------------------------------------------
extern "C" void kernel_launch(void* const* d_in, const int* in_sizes, int n_in,
                              void* d_out, int out_size) {
    const float* bases_full = (const float*)d_in[0];
    const float* top_feats  = (const float*)d_in[1];
    const float* locations  = (const float*)d_in[2];
    const float* atten_W    = (const float*)d_in[3];
    const float* atten_b    = (const float*)d_in[4];
    const float* sizes      = (const float*)d_in[5];
    const int*   fpn_levels = (const int*)d_in[6];
    float* out = (float*)d_out;

    gemm_partial<<<dim3((ATTN_LEN + 15) / 16, KSPLIT), 128>>>(top_feats, atten_W);
    prep_bases_frag<<<NT16, 256>>>(bases_full);
    reduce_and_bfrag<<<NINST, 512>>>(atten_b);

    mlp_mma16<<<dim3(GX, IGY), 256>>>(locations, sizes, fpn_levels, out);

    argmax_kernel<<<NINST * NKP, 256>>>(out, bases_full);
}

// round 16
// speedup vs baseline: 1.5269x; 1.5269x over previous
#include <cuda_runtime.h>
#include <cuda_fp16.h>
#include <cstdint>

#define NINST 64
#define HDIM 100
#define WDIM 152
#define HW 15200
#define NB 32
#define NKP 17
#define ATTN_LEN 2737
#define KDIM 2304
#define KSPLIT 8
#define KCHUNK (KDIM / KSPLIT)   // 288
#define IPB 4                    // instances per mlp CTA
#define IGY (NINST / IPB)        // 16
#define GX 60                    // ceil(HW / 256)
#define NQ16 22                  // uint4 B-fragment entries per instance per lane
#define BFRAG16 (NQ16 * 32)      // 704 uint4 per instance
#define NT16 950                 // HW / 16 (m16 tiles)

typedef unsigned long long ull;

__device__ float g_attns[NINST * ATTN_LEN];
__device__ float g_part[KSPLIT * NINST * ATTN_LEN];
__device__ uint4 g_bfrag[NINST * BFRAG16];
__device__ uint2 g_bbf[NT16 * 256];   // layer-1 A frags: [tile16][e(8)][lane(32)] (hi,lo)

// ---------------- packed f32x2 helpers (gemm) ----------------
__device__ __forceinline__ ull pack2(float x, float y) {
    ull r; asm("mov.b64 %0, {%1, %2};" : "=l"(r) : "f"(x), "f"(y)); return r;
}
__device__ __forceinline__ ull ffma2(ull a, ull b, ull c) {
    ull d; asm("fma.rn.f32x2 %0, %1, %2, %3;" : "=l"(d) : "l"(a), "l"(b), "l"(c)); return d;
}
__device__ __forceinline__ float2 unpack2(ull v) {
    float2 r; asm("mov.b64 {%0, %1}, %2;" : "=f"(r.x), "=f"(r.y) : "l"(v)); return r;
}

// ---------------- fp16 split helpers ----------------
__device__ __forceinline__ void h2_split(float x0, float x1, uint32_t& hi, uint32_t& lo) {
    unsigned short s0 = __half_as_ushort(__float2half_rn(x0));
    unsigned short s1 = __half_as_ushort(__float2half_rn(x1));
    float l0 = x0 - __half2float(__ushort_as_half(s0));
    float l1 = x1 - __half2float(__ushort_as_half(s1));
    unsigned short t0 = __half_as_ushort(__float2half_rn(l0));
    unsigned short t1 = __half_as_ushort(__float2half_rn(l1));
    hi = (uint32_t)s0 | ((uint32_t)s1 << 16);
    lo = (uint32_t)t0 | ((uint32_t)t1 << 16);
}
__device__ __forceinline__ void mma_f16(float* c, const uint32_t* a, uint32_t b0, uint32_t b1) {
    asm volatile(
        "mma.sync.aligned.m16n8k16.row.col.f32.f16.f16.f32 "
        "{%0,%1,%2,%3}, {%4,%5,%6,%7}, {%8,%9}, {%0,%1,%2,%3};"
        : "+f"(c[0]), "+f"(c[1]), "+f"(c[2]), "+f"(c[3])
        : "r"(a[0]), "r"(a[1]), "r"(a[2]), "r"(a[3]), "r"(b0), "r"(b1));
}

// ---------------------------------------------------------------------------
// Kernel A1: split-K partial GEMM (fp32, exact — R11 version).
// ---------------------------------------------------------------------------
__global__ __launch_bounds__(128) void gemm_partial(const float* __restrict__ A,
                                                    const float* __restrict__ Wm) {
    __shared__ __align__(16) float As[32][64];
    __shared__ __align__(16) float Ws[32][16];
    int tid = threadIdx.x;
    int jblk = blockIdx.x * 16;
    int kbase = blockIdx.y * KCHUNK;

    int an = tid >> 1;
    int ak = (tid & 1) * 16;
    int wj = tid >> 3;
    int wk = (tid & 7) * 4;
    int n0 = (tid & 15) * 4;
    int j0 = (tid >> 4) * 2;

    ull acc2[2][2];
    acc2[0][0] = acc2[0][1] = acc2[1][0] = acc2[1][1] = 0ULL;

    for (int k0 = kbase; k0 < kbase + KCHUNK; k0 += 32) {
        __syncthreads();
        const float4* ap = (const float4*)(A + (size_t)an * KDIM + k0 + ak);
#pragma unroll
        for (int v = 0; v < 4; v++) {
            float4 t = ap[v];
            As[ak + v * 4 + 0][an] = t.x;
            As[ak + v * 4 + 1][an] = t.y;
            As[ak + v * 4 + 2][an] = t.z;
            As[ak + v * 4 + 3][an] = t.w;
        }
        {
            int j = jblk + wj;
            float4 t = make_float4(0.f, 0.f, 0.f, 0.f);
            if (j < ATTN_LEN)
                t = *(const float4*)(Wm + (size_t)j * KDIM + k0 + wk);
            Ws[wk + 0][wj] = t.x;
            Ws[wk + 1][wj] = t.y;
            Ws[wk + 2][wj] = t.z;
            Ws[wk + 3][wj] = t.w;
        }
        __syncthreads();
#pragma unroll
        for (int kk = 0; kk < 32; kk++) {
            ulonglong2 a2 = *(const ulonglong2*)&As[kk][n0];
            float2 wf = *(const float2*)&Ws[kk][j0];
            ull wx = pack2(wf.x, wf.x);
            ull wy = pack2(wf.y, wf.y);
            acc2[0][0] = ffma2(a2.x, wx, acc2[0][0]);
            acc2[0][1] = ffma2(a2.x, wy, acc2[0][1]);
            acc2[1][0] = ffma2(a2.y, wx, acc2[1][0]);
            acc2[1][1] = ffma2(a2.y, wy, acc2[1][1]);
        }
    }
    float* outp = g_part + (size_t)blockIdx.y * NINST * ATTN_LEN;
#pragma unroll
    for (int p = 0; p < 2; p++) {
#pragma unroll
        for (int dj = 0; dj < 2; dj++) {
            int j = jblk + j0 + dj;
            if (j < ATTN_LEN) {
                float2 u = unpack2(acc2[p][dj]);
                outp[(size_t)(n0 + 2 * p)     * ATTN_LEN + j] = u.x;
                outp[(size_t)(n0 + 2 * p + 1) * ATTN_LEN + j] = u.y;
            }
        }
    }
}

// ---------------------------------------------------------------------------
// Kernel A2+A3 fused: per-instance split-K reduce + bias, then build fp16
// B fragments from the freshly written row (block-local write->sync->read).
// ---------------------------------------------------------------------------
__global__ __launch_bounds__(512) void reduce_and_bfrag(const float* __restrict__ bias) {
    int n = blockIdx.x;
    int tid = threadIdx.x;
    float* row = g_attns + (size_t)n * ATTN_LEN;

    for (int j = tid; j < ATTN_LEN; j += 512) {
        size_t idx = (size_t)n * ATTN_LEN + j;
        float s = 0.f;
#pragma unroll
        for (int p = 0; p < KSPLIT; p++) s += g_part[(size_t)p * NINST * ATTN_LEN + idx];
        row[j] = s + bias[j];
    }
    __syncthreads();

    uint4* dst = g_bfrag + (size_t)n * BFRAG16;
    for (int e = tid; e < BFRAG16; e += 512) {
        int lane = e & 31;
        int q = e >> 5;
        int layer, qq;
        if (q < 8)       { layer = 0; qq = q; }
        else if (q < 16) { layer = 1; qq = q - 8; }
        else             { layer = 2; qq = q - 16; }
        int nt = qq >> 1, kt = qq & 1;
        int g = lane >> 2, tig = lane & 3;
        int o = nt * 8 + g;
        int c0 = kt * 16 + 2 * tig;

        float x0 = 0.f, x1 = 0.f, x2 = 0.f, x3 = 0.f;
        if (layer == 0) {
            x0 = row[o * 34 + c0 + 2];  x1 = row[o * 34 + c0 + 3];
            x2 = row[o * 34 + c0 + 10]; x3 = row[o * 34 + c0 + 11];
        } else if (layer == 1) {
            x0 = row[1120 + o * 32 + c0];     x1 = row[1120 + o * 32 + c0 + 1];
            x2 = row[1120 + o * 32 + c0 + 8]; x3 = row[1120 + o * 32 + c0 + 9];
        } else if (o < NKP) {
            x0 = row[2176 + o * 32 + c0];     x1 = row[2176 + o * 32 + c0 + 1];
            x2 = row[2176 + o * 32 + c0 + 8]; x3 = row[2176 + o * 32 + c0 + 9];
        }
        uint32_t h0, l0, h1, l1;
        h2_split(x0, x1, h0, l0);
        h2_split(x2, x3, h1, l1);
        dst[e] = make_uint4(h0, h1, l0, l1);
    }
}

// ---------------------------------------------------------------------------
// Kernel A4: pre-build layer-1 A fragments in fragment-major layout.
// ---------------------------------------------------------------------------
__global__ __launch_bounds__(256) void prep_bases_frag(const float* __restrict__ bases_full) {
    int tile = blockIdx.x;
    int tid = threadIdx.x;
    int lane = tid & 31, e = tid >> 5;
    int g = lane >> 2, tig = lane & 3;
    int kt = e >> 2, r = e & 3;
    int px = tile * 16 + g + ((r & 1) << 3);
    int p = kt * 8 + ((r >> 1) << 2) + tig;
    float x0 = bases_full[(size_t)(2 * p)     * HW + px];
    float x1 = bases_full[(size_t)(2 * p + 1) * HW + px];
    uint32_t hi, lo;
    h2_split(x0, x1, hi, lo);
    g_bbf[tile * 256 + e * 32 + lane] = make_uint2(hi, lo);
}

// ---------------------------------------------------------------------------
// Kernel B: MLP via mma.sync m16n8k16 fp16 (2-way split, 3 passes), fully
// register-resident, mt-INNER (B-frag reuse across both m-tiles — exact
// R11/R13 best-known structure).
// ---------------------------------------------------------------------------
__global__ __launch_bounds__(256, 2) void mlp_mma16(const float* __restrict__ locations,
                                                    const float* __restrict__ sizes,
                                                    const int* __restrict__ fpn_levels,
                                                    float* __restrict__ out) {
    int tid = threadIdx.x;
    int warp = tid >> 5;
    int lane = tid & 31;
    int g = lane >> 2, tig = lane & 3;

    int pxb = blockIdx.x * 256 + warp * 32;
    if (pxb >= HW) return;
    int t0 = pxb >> 4;

    float gxv[4], gyv[4];
#pragma unroll
    for (int r = 0; r < 4; r++) {
        int p = pxb + (r >> 1) * 16 + g + (r & 1) * 8;
        gxv[r] = (float)(p % WDIM) * 8.f + 4.f;
        gyv[r] = (float)(p / WDIM) * 8.f + 4.f;
    }

    int nbase = blockIdx.y * IPB;
    for (int ii = 0; ii < IPB; ii++) {
        int n = nbase + ii;
        const uint4* bf = g_bfrag + (size_t)n * BFRAG16;
        const float* row = g_attns + (size_t)n * ATTN_LEN;
        float invr = 1.f / sizes[fpn_levels[n]];
        float lx = locations[2 * n], ly = locations[2 * n + 1];

        uint32_t ah[2][8], al[2][8];
        float cc[2][4][4];

        // ---------- layer 1: A from fragment-major global (coalesced) ----------
#pragma unroll
        for (int mt = 0; mt < 2; mt++)
#pragma unroll
            for (int e = 0; e < 8; e++) {
                uint2 u = __ldg(&g_bbf[(t0 + mt) * 256 + e * 32 + lane]);
                ah[mt][e] = u.x;
                al[mt][e] = u.y;
            }
#pragma unroll
        for (int mt = 0; mt < 2; mt++)
#pragma unroll
            for (int nt = 0; nt < 4; nt++)
#pragma unroll
                for (int j = 0; j < 4; j++) cc[mt][nt][j] = 0.f;
#pragma unroll
        for (int nt = 0; nt < 4; nt++)
#pragma unroll
            for (int kt = 0; kt < 2; kt++) {
                uint4 f = __ldg(bf + (nt * 2 + kt) * 32 + lane);
#pragma unroll
                for (int mt = 0; mt < 2; mt++) {
                    mma_f16(cc[mt][nt], &ah[mt][kt * 4], f.x, f.y);
                    mma_f16(cc[mt][nt], &ah[mt][kt * 4], f.z, f.w);
                    mma_f16(cc[mt][nt], &al[mt][kt * 4], f.x, f.y);
                }
            }
        // epilogue L1: offsets + bias + relu, rebuild A frags in registers
#pragma unroll
        for (int mt = 0; mt < 2; mt++) {
            float ox0 = (lx - gxv[2 * mt]) * invr,     oy0 = (ly - gyv[2 * mt]) * invr;
            float ox1 = (lx - gxv[2 * mt + 1]) * invr, oy1 = (ly - gyv[2 * mt + 1]) * invr;
#pragma unroll
            for (int kt = 0; kt < 2; kt++)
#pragma unroll
                for (int h = 0; h < 2; h++) {
                    int nt = 2 * kt + h;
                    int o0 = nt * 8 + 2 * tig, o1 = o0 + 1;
                    float wx0 = row[o0 * 34], wy0 = row[o0 * 34 + 1], bb0 = row[1088 + o0];
                    float wx1 = row[o1 * 34], wy1 = row[o1 * 34 + 1], bb1 = row[1088 + o1];
                    float v00 = fmaxf(cc[mt][nt][0] + wx0 * ox0 + wy0 * oy0 + bb0, 0.f);
                    float v01 = fmaxf(cc[mt][nt][1] + wx1 * ox0 + wy1 * oy0 + bb1, 0.f);
                    float v10 = fmaxf(cc[mt][nt][2] + wx0 * ox1 + wy0 * oy1 + bb0, 0.f);
                    float v11 = fmaxf(cc[mt][nt][3] + wx1 * ox1 + wy1 * oy1 + bb1, 0.f);
                    h2_split(v00, v01, ah[mt][kt * 4 + 2 * h + 0], al[mt][kt * 4 + 2 * h + 0]);
                    h2_split(v10, v11, ah[mt][kt * 4 + 2 * h + 1], al[mt][kt * 4 + 2 * h + 1]);
                }
        }

        // ---------- layer 2 ----------
#pragma unroll
        for (int mt = 0; mt < 2; mt++)
#pragma unroll
            for (int nt = 0; nt < 4; nt++)
#pragma unroll
                for (int j = 0; j < 4; j++) cc[mt][nt][j] = 0.f;
#pragma unroll
        for (int nt = 0; nt < 4; nt++)
#pragma unroll
            for (int kt = 0; kt < 2; kt++) {
                uint4 f = __ldg(bf + (8 + nt * 2 + kt) * 32 + lane);
#pragma unroll
                for (int mt = 0; mt < 2; mt++) {
                    mma_f16(cc[mt][nt], &ah[mt][kt * 4], f.x, f.y);
                    mma_f16(cc[mt][nt], &ah[mt][kt * 4], f.z, f.w);
                    mma_f16(cc[mt][nt], &al[mt][kt * 4], f.x, f.y);
                }
            }
#pragma unroll
        for (int mt = 0; mt < 2; mt++)
#pragma unroll
            for (int kt = 0; kt < 2; kt++)
#pragma unroll
                for (int h = 0; h < 2; h++) {
                    int nt = 2 * kt + h;
                    int o0 = nt * 8 + 2 * tig, o1 = o0 + 1;
                    float bb0 = row[2144 + o0], bb1 = row[2144 + o1];
                    float v00 = fmaxf(cc[mt][nt][0] + bb0, 0.f);
                    float v01 = fmaxf(cc[mt][nt][1] + bb1, 0.f);
                    float v10 = fmaxf(cc[mt][nt][2] + bb0, 0.f);
                    float v11 = fmaxf(cc[mt][nt][3] + bb1, 0.f);
                    h2_split(v00, v01, ah[mt][kt * 4 + 2 * h + 0], al[mt][kt * 4 + 2 * h + 0]);
                    h2_split(v10, v11, ah[mt][kt * 4 + 2 * h + 1], al[mt][kt * 4 + 2 * h + 1]);
                }

        // ---------- layer 3 (nt 0..2, write o < 17) ----------
#pragma unroll
        for (int mt = 0; mt < 2; mt++)
#pragma unroll
            for (int nt = 0; nt < 3; nt++)
#pragma unroll
                for (int j = 0; j < 4; j++) cc[mt][nt][j] = 0.f;
#pragma unroll
        for (int nt = 0; nt < 3; nt++)
#pragma unroll
            for (int kt = 0; kt < 2; kt++) {
                uint4 f = __ldg(bf + (16 + nt * 2 + kt) * 32 + lane);
#pragma unroll
                for (int mt = 0; mt < 2; mt++) {
                    mma_f16(cc[mt][nt], &ah[mt][kt * 4], f.x, f.y);
                    mma_f16(cc[mt][nt], &ah[mt][kt * 4], f.z, f.w);
                    mma_f16(cc[mt][nt], &al[mt][kt * 4], f.x, f.y);
                }
            }
        float* ob = out + (size_t)n * NKP * HW;
#pragma unroll
        for (int mt = 0; mt < 2; mt++) {
            int px0 = pxb + 16 * mt + g, px1 = px0 + 8;
#pragma unroll
            for (int nt = 0; nt < 3; nt++) {
                int o0 = nt * 8 + 2 * tig, o1 = o0 + 1;
                if (o0 < NKP) {
                    float bb0 = row[2720 + o0];
                    ob[(size_t)o0 * HW + px0] = cc[mt][nt][0] + bb0;
                    ob[(size_t)o0 * HW + px1] = cc[mt][nt][2] + bb0;
                }
                if (o1 < NKP) {
                    float bb1 = row[2720 + o1];
                    ob[(size_t)o1 * HW + px0] = cc[mt][nt][1] + bb1;
                    ob[(size_t)o1 * HW + px1] = cc[mt][nt][3] + bb1;
                }
            }
        }
    }
}

// ---------------------------------------------------------------------------
// Kernel C: per (n, kp) argmax over HW, 4 independent accumulator chains,
// first-index tie-break preserved.
// ---------------------------------------------------------------------------
__global__ __launch_bounds__(256) void argmax_kernel(float* __restrict__ out,
                                                     const float* __restrict__ bases_full) {
    int pair = blockIdx.x;
    int k = pair % NKP;
    const float4* lg = (const float4*)(out + (size_t)pair * HW);
    int tid = threadIdx.x;

    float bv0 = -3.4e38f, bv1 = -3.4e38f, bv2 = -3.4e38f, bv3 = -3.4e38f;
    int bi0 = 0, bi1 = 1, bi2 = 2, bi3 = 3;
    for (int q = tid; q < HW / 4; q += 256) {
        float4 v = lg[q];
        int i0 = q * 4;
        if (v.x > bv0) { bv0 = v.x; bi0 = i0; }
        if (v.y > bv1) { bv1 = v.y; bi1 = i0 + 1; }
        if (v.z > bv2) { bv2 = v.z; bi2 = i0 + 2; }
        if (v.w > bv3) { bv3 = v.w; bi3 = i0 + 3; }
    }
    float best = bv0; int bi = bi0;
    if (bv1 > best || (bv1 == best && bi1 < bi)) { best = bv1; bi = bi1; }
    if (bv2 > best || (bv2 == best && bi2 < bi)) { best = bv2; bi = bi2; }
    if (bv3 > best || (bv3 == best && bi3 < bi)) { best = bv3; bi = bi3; }

    __shared__ float sv[256];
    __shared__ int si[256];
    sv[tid] = best;
    si[tid] = bi;
    __syncthreads();
#pragma unroll
    for (int s = 128; s > 0; s >>= 1) {
        if (tid < s) {
            float ov = sv[tid + s]; int oi = si[tid + s];
            if (ov > sv[tid] || (ov == sv[tid] && oi < si[tid])) {
                sv[tid] = ov; si[tid] = oi;
            }
        }
        __syncthreads();
    }
    if (tid == 0) {
        int i = si[0];
        float gx = (float)(i % WDIM) * 8.f + 4.f;
        float gy = (float)(i / WDIM) * 8.f + 4.f;
        float* kp = out + (size_t)NINST * NKP * HW + (size_t)pair * 2;
        kp[0] = bases_full[(size_t)(NB + 2 * k)     * HW + i] + gx;
        kp[1] = bases_full[(size_t)(NB + 2 * k + 1) * HW + i] + gy;
    }
}

// ---------------------------------------------------------------------------
extern "C" void kernel_launch(void* const* d_in, const int* in_sizes, int n_in,
                              void* d_out, int out_size) {
    const float* bases_full = (const float*)d_in[0];
    const float* top_feats  = (const float*)d_in[1];
    const float* locations  = (const float*)d_in[2];
    const float* atten_W    = (const float*)d_in[3];
    const float* atten_b    = (const float*)d_in[4];
    const float* sizes      = (const float*)d_in[5];
    const int*   fpn_levels = (const int*)d_in[6];
    float* out = (float*)d_out;

    gemm_partial<<<dim3((ATTN_LEN + 15) / 16, KSPLIT), 128>>>(top_feats, atten_W);
    prep_bases_frag<<<NT16, 256>>>(bases_full);
    reduce_and_bfrag<<<NINST, 512>>>(atten_b);

    mlp_mma16<<<dim3(GX, IGY), 256>>>(locations, sizes, fpn_levels, out);

    argmax_kernel<<<NINST * NKP, 256>>>(out, bases_full);
}

// round 17
// speedup vs baseline: 1.6316x; 1.0686x over previous
#include <cuda_runtime.h>
#include <cuda_fp16.h>
#include <cstdint>

#define NINST 64
#define HDIM 100
#define WDIM 152
#define HW 15200
#define NB 32
#define NKP 17
#define ATTN_LEN 2737
#define KDIM 2304
#define KSPLIT 8
#define KCHUNK (KDIM / KSPLIT)   // 288
#define GX 60                    // ceil(HW / 256)
#define NQ16 22                  // uint4 B-fragment entries per instance per lane
#define BFRAG16 (NQ16 * 32)      // 704 uint4 per instance
#define NT16 950                 // HW / 16 (m16 tiles)
#define GEMM_BLKS (172 * KSPLIT) // 1376
#define RED_BLKS 192             // reduce blocks in fused reduce/bfrag kernel

typedef unsigned long long ull;

__device__ float g_attns[NINST * ATTN_LEN];
__device__ float g_part[KSPLIT * NINST * ATTN_LEN];
__device__ uint4 g_bfrag[NINST * BFRAG16];
__device__ uint2 g_bbf[NT16 * 256];   // layer-1 A frags: [tile16][e(8)][lane(32)] (hi,lo)

// ---------------- packed f32x2 helpers (gemm) ----------------
__device__ __forceinline__ ull pack2(float x, float y) {
    ull r; asm("mov.b64 %0, {%1, %2};" : "=l"(r) : "f"(x), "f"(y)); return r;
}
__device__ __forceinline__ ull ffma2(ull a, ull b, ull c) {
    ull d; asm("fma.rn.f32x2 %0, %1, %2, %3;" : "=l"(d) : "l"(a), "l"(b), "l"(c)); return d;
}
__device__ __forceinline__ float2 unpack2(ull v) {
    float2 r; asm("mov.b64 {%0, %1}, %2;" : "=f"(r.x), "=f"(r.y) : "l"(v)); return r;
}

// ---------------- fp16 split helpers ----------------
__device__ __forceinline__ void h2_split(float x0, float x1, uint32_t& hi, uint32_t& lo) {
    unsigned short s0 = __half_as_ushort(__float2half_rn(x0));
    unsigned short s1 = __half_as_ushort(__float2half_rn(x1));
    float l0 = x0 - __half2float(__ushort_as_half(s0));
    float l1 = x1 - __half2float(__ushort_as_half(s1));
    unsigned short t0 = __half_as_ushort(__float2half_rn(l0));
    unsigned short t1 = __half_as_ushort(__float2half_rn(l1));
    hi = (uint32_t)s0 | ((uint32_t)s1 << 16);
    lo = (uint32_t)t0 | ((uint32_t)t1 << 16);
}
__device__ __forceinline__ void mma_f16(float* c, const uint32_t* a, uint32_t b0, uint32_t b1) {
    asm volatile(
        "mma.sync.aligned.m16n8k16.row.col.f32.f16.f16.f32 "
        "{%0,%1,%2,%3}, {%4,%5,%6,%7}, {%8,%9}, {%0,%1,%2,%3};"
        : "+f"(c[0]), "+f"(c[1]), "+f"(c[2]), "+f"(c[3])
        : "r"(a[0]), "r"(a[1]), "r"(a[2]), "r"(a[3]), "r"(b0), "r"(b1));
}

// split-K reduce in the SAME order everywhere -> bit-identical values
__device__ __forceinline__ float red8(int n, int j, const float* __restrict__ bias) {
    size_t idx = (size_t)n * ATTN_LEN + j;
    float s = 0.f;
#pragma unroll
    for (int p = 0; p < KSPLIT; p++) s += g_part[(size_t)p * NINST * ATTN_LEN + idx];
    return s + bias[j];
}

// ---------------------------------------------------------------------------
// Kernel A1: fused split-K partial GEMM (blocks < GEMM_BLKS) + bases-frag
// prep (remaining NT16 blocks) — independent work, one launch.
// ---------------------------------------------------------------------------
__global__ __launch_bounds__(128) void gemm_prep(const float* __restrict__ A,
                                                 const float* __restrict__ Wm,
                                                 const float* __restrict__ bases_full) {
    __shared__ __align__(16) float As[32][64];
    __shared__ __align__(16) float Ws[32][16];
    int b = blockIdx.x;
    int tid = threadIdx.x;

    if (b >= GEMM_BLKS) {
        // ---- bases fragment prep: tile = b - GEMM_BLKS, 256 entries ----
        int tile = b - GEMM_BLKS;
#pragma unroll
        for (int s = 0; s < 2; s++) {
            int idx = tid + s * 128;
            int lane = idx & 31, e = idx >> 5;
            int g = lane >> 2, tig = lane & 3;
            int kt = e >> 2, r = e & 3;
            int px = tile * 16 + g + ((r & 1) << 3);
            int p = kt * 8 + ((r >> 1) << 2) + tig;
            float x0 = bases_full[(size_t)(2 * p)     * HW + px];
            float x1 = bases_full[(size_t)(2 * p + 1) * HW + px];
            uint32_t hi, lo;
            h2_split(x0, x1, hi, lo);
            g_bbf[tile * 256 + e * 32 + lane] = make_uint2(hi, lo);
        }
        return;
    }

    // ---- gemm block ----
    int jblk = (b % 172) * 16;
    int kbase = (b / 172) * KCHUNK;

    int an = tid >> 1;
    int ak = (tid & 1) * 16;
    int wj = tid >> 3;
    int wk = (tid & 7) * 4;
    int n0 = (tid & 15) * 4;
    int j0 = (tid >> 4) * 2;

    ull acc2[2][2];
    acc2[0][0] = acc2[0][1] = acc2[1][0] = acc2[1][1] = 0ULL;

    for (int k0 = kbase; k0 < kbase + KCHUNK; k0 += 32) {
        __syncthreads();
        const float4* ap = (const float4*)(A + (size_t)an * KDIM + k0 + ak);
#pragma unroll
        for (int v = 0; v < 4; v++) {
            float4 t = ap[v];
            As[ak + v * 4 + 0][an] = t.x;
            As[ak + v * 4 + 1][an] = t.y;
            As[ak + v * 4 + 2][an] = t.z;
            As[ak + v * 4 + 3][an] = t.w;
        }
        {
            int j = jblk + wj;
            float4 t = make_float4(0.f, 0.f, 0.f, 0.f);
            if (j < ATTN_LEN)
                t = *(const float4*)(Wm + (size_t)j * KDIM + k0 + wk);
            Ws[wk + 0][wj] = t.x;
            Ws[wk + 1][wj] = t.y;
            Ws[wk + 2][wj] = t.z;
            Ws[wk + 3][wj] = t.w;
        }
        __syncthreads();
#pragma unroll
        for (int kk = 0; kk < 32; kk++) {
            ulonglong2 a2 = *(const ulonglong2*)&As[kk][n0];
            float2 wf = *(const float2*)&Ws[kk][j0];
            ull wx = pack2(wf.x, wf.x);
            ull wy = pack2(wf.y, wf.y);
            acc2[0][0] = ffma2(a2.x, wx, acc2[0][0]);
            acc2[0][1] = ffma2(a2.x, wy, acc2[0][1]);
            acc2[1][0] = ffma2(a2.y, wx, acc2[1][0]);
            acc2[1][1] = ffma2(a2.y, wy, acc2[1][1]);
        }
    }
    float* outp = g_part + (size_t)(b / 172) * NINST * ATTN_LEN;
#pragma unroll
    for (int p = 0; p < 2; p++) {
#pragma unroll
        for (int dj = 0; dj < 2; dj++) {
            int j = jblk + j0 + dj;
            if (j < ATTN_LEN) {
                float2 u = unpack2(acc2[p][dj]);
                outp[(size_t)(n0 + 2 * p)     * ATTN_LEN + j] = u.x;
                outp[(size_t)(n0 + 2 * p + 1) * ATTN_LEN + j] = u.y;
            }
        }
    }
}

// ---------------------------------------------------------------------------
// Kernel A2: fused (independent phases): blocks < NINST build B-fragments
// reading g_part directly (same reduce order -> bit-identical); remaining
// RED_BLKS blocks compute g_attns = reduce + bias (grid-strided).
// ---------------------------------------------------------------------------
__global__ __launch_bounds__(512) void reduce_bfrag(const float* __restrict__ bias) {
    int b = blockIdx.x;
    int tid = threadIdx.x;

    if (b < NINST) {
        int n = b;
        uint4* dst = g_bfrag + (size_t)n * BFRAG16;
        for (int e = tid; e < BFRAG16; e += 512) {
            int lane = e & 31;
            int q = e >> 5;
            int layer, qq;
            if (q < 8)       { layer = 0; qq = q; }
            else if (q < 16) { layer = 1; qq = q - 8; }
            else             { layer = 2; qq = q - 16; }
            int nt = qq >> 1, kt = qq & 1;
            int g = lane >> 2, tig = lane & 3;
            int o = nt * 8 + g;
            int c0 = kt * 16 + 2 * tig;

            float x0 = 0.f, x1 = 0.f, x2 = 0.f, x3 = 0.f;
            if (layer == 0) {
                x0 = red8(n, o * 34 + c0 + 2, bias);  x1 = red8(n, o * 34 + c0 + 3, bias);
                x2 = red8(n, o * 34 + c0 + 10, bias); x3 = red8(n, o * 34 + c0 + 11, bias);
            } else if (layer == 1) {
                x0 = red8(n, 1120 + o * 32 + c0, bias);     x1 = red8(n, 1120 + o * 32 + c0 + 1, bias);
                x2 = red8(n, 1120 + o * 32 + c0 + 8, bias); x3 = red8(n, 1120 + o * 32 + c0 + 9, bias);
            } else if (o < NKP) {
                x0 = red8(n, 2176 + o * 32 + c0, bias);     x1 = red8(n, 2176 + o * 32 + c0 + 1, bias);
                x2 = red8(n, 2176 + o * 32 + c0 + 8, bias); x3 = red8(n, 2176 + o * 32 + c0 + 9, bias);
            }
            uint32_t h0, l0, h1, l1;
            h2_split(x0, x1, h0, l0);
            h2_split(x2, x3, h1, l1);
            dst[e] = make_uint4(h0, h1, l0, l1);
        }
    } else {
        int base = (b - NINST) * 512 + tid;
        for (int idx = base; idx < NINST * ATTN_LEN; idx += RED_BLKS * 512) {
            int n = idx / ATTN_LEN, j = idx - n * ATTN_LEN;
            g_attns[idx] = red8(n, j, bias);
        }
    }
}

// ---------------------------------------------------------------------------
// Kernel B: MLP via mma.sync m16n8k16 fp16 (2-way split, 3 passes), fully
// register-resident, mt-INNER. IPB=1: grid (60, 64) = 3840 blocks for
// near-perfect wave packing (13 waves at 296 concurrent ~= 12.97 ideal).
// ---------------------------------------------------------------------------
__global__ __launch_bounds__(256, 2) void mlp_mma16(const float* __restrict__ locations,
                                                    const float* __restrict__ sizes,
                                                    const int* __restrict__ fpn_levels,
                                                    float* __restrict__ out) {
    int tid = threadIdx.x;
    int warp = tid >> 5;
    int lane = tid & 31;
    int g = lane >> 2, tig = lane & 3;

    int pxb = blockIdx.x * 256 + warp * 32;
    if (pxb >= HW) return;
    int t0 = pxb >> 4;

    float gxv[4], gyv[4];
#pragma unroll
    for (int r = 0; r < 4; r++) {
        int p = pxb + (r >> 1) * 16 + g + (r & 1) * 8;
        gxv[r] = (float)(p % WDIM) * 8.f + 4.f;
        gyv[r] = (float)(p / WDIM) * 8.f + 4.f;
    }

    int n = blockIdx.y;
    const uint4* bf = g_bfrag + (size_t)n * BFRAG16;
    const float* row = g_attns + (size_t)n * ATTN_LEN;
    float invr = 1.f / sizes[fpn_levels[n]];
    float lx = locations[2 * n], ly = locations[2 * n + 1];

    uint32_t ah[2][8], al[2][8];
    float cc[2][4][4];

    // ---------- layer 1: A from fragment-major global (coalesced) ----------
#pragma unroll
    for (int mt = 0; mt < 2; mt++)
#pragma unroll
        for (int e = 0; e < 8; e++) {
            uint2 u = __ldg(&g_bbf[(t0 + mt) * 256 + e * 32 + lane]);
            ah[mt][e] = u.x;
            al[mt][e] = u.y;
        }
#pragma unroll
    for (int mt = 0; mt < 2; mt++)
#pragma unroll
        for (int nt = 0; nt < 4; nt++)
#pragma unroll
            for (int j = 0; j < 4; j++) cc[mt][nt][j] = 0.f;
#pragma unroll
    for (int nt = 0; nt < 4; nt++)
#pragma unroll
        for (int kt = 0; kt < 2; kt++) {
            uint4 f = __ldg(bf + (nt * 2 + kt) * 32 + lane);
#pragma unroll
            for (int mt = 0; mt < 2; mt++) {
                mma_f16(cc[mt][nt], &ah[mt][kt * 4], f.x, f.y);
                mma_f16(cc[mt][nt], &ah[mt][kt * 4], f.z, f.w);
                mma_f16(cc[mt][nt], &al[mt][kt * 4], f.x, f.y);
            }
        }
    // epilogue L1: offsets + bias + relu, rebuild A frags in registers
#pragma unroll
    for (int mt = 0; mt < 2; mt++) {
        float ox0 = (lx - gxv[2 * mt]) * invr,     oy0 = (ly - gyv[2 * mt]) * invr;
        float ox1 = (lx - gxv[2 * mt + 1]) * invr, oy1 = (ly - gyv[2 * mt + 1]) * invr;
#pragma unroll
        for (int kt = 0; kt < 2; kt++)
#pragma unroll
            for (int h = 0; h < 2; h++) {
                int nt = 2 * kt + h;
                int o0 = nt * 8 + 2 * tig, o1 = o0 + 1;
                float wx0 = row[o0 * 34], wy0 = row[o0 * 34 + 1], bb0 = row[1088 + o0];
                float wx1 = row[o1 * 34], wy1 = row[o1 * 34 + 1], bb1 = row[1088 + o1];
                float v00 = fmaxf(cc[mt][nt][0] + wx0 * ox0 + wy0 * oy0 + bb0, 0.f);
                float v01 = fmaxf(cc[mt][nt][1] + wx1 * ox0 + wy1 * oy0 + bb1, 0.f);
                float v10 = fmaxf(cc[mt][nt][2] + wx0 * ox1 + wy0 * oy1 + bb0, 0.f);
                float v11 = fmaxf(cc[mt][nt][3] + wx1 * ox1 + wy1 * oy1 + bb1, 0.f);
                h2_split(v00, v01, ah[mt][kt * 4 + 2 * h + 0], al[mt][kt * 4 + 2 * h + 0]);
                h2_split(v10, v11, ah[mt][kt * 4 + 2 * h + 1], al[mt][kt * 4 + 2 * h + 1]);
            }
    }

    // ---------- layer 2 ----------
#pragma unroll
    for (int mt = 0; mt < 2; mt++)
#pragma unroll
        for (int nt = 0; nt < 4; nt++)
#pragma unroll
            for (int j = 0; j < 4; j++) cc[mt][nt][j] = 0.f;
#pragma unroll
    for (int nt = 0; nt < 4; nt++)
#pragma unroll
        for (int kt = 0; kt < 2; kt++) {
            uint4 f = __ldg(bf + (8 + nt * 2 + kt) * 32 + lane);
#pragma unroll
            for (int mt = 0; mt < 2; mt++) {
                mma_f16(cc[mt][nt], &ah[mt][kt * 4], f.x, f.y);
                mma_f16(cc[mt][nt], &ah[mt][kt * 4], f.z, f.w);
                mma_f16(cc[mt][nt], &al[mt][kt * 4], f.x, f.y);
            }
        }
#pragma unroll
    for (int mt = 0; mt < 2; mt++)
#pragma unroll
        for (int kt = 0; kt < 2; kt++)
#pragma unroll
            for (int h = 0; h < 2; h++) {
                int nt = 2 * kt + h;
                int o0 = nt * 8 + 2 * tig, o1 = o0 + 1;
                float bb0 = row[2144 + o0], bb1 = row[2144 + o1];
                float v00 = fmaxf(cc[mt][nt][0] + bb0, 0.f);
                float v01 = fmaxf(cc[mt][nt][1] + bb1, 0.f);
                float v10 = fmaxf(cc[mt][nt][2] + bb0, 0.f);
                float v11 = fmaxf(cc[mt][nt][3] + bb1, 0.f);
                h2_split(v00, v01, ah[mt][kt * 4 + 2 * h + 0], al[mt][kt * 4 + 2 * h + 0]);
                h2_split(v10, v11, ah[mt][kt * 4 + 2 * h + 1], al[mt][kt * 4 + 2 * h + 1]);
            }

    // ---------- layer 3 (nt 0..2, write o < 17) ----------
#pragma unroll
    for (int mt = 0; mt < 2; mt++)
#pragma unroll
        for (int nt = 0; nt < 3; nt++)
#pragma unroll
            for (int j = 0; j < 4; j++) cc[mt][nt][j] = 0.f;
#pragma unroll
    for (int nt = 0; nt < 3; nt++)
#pragma unroll
        for (int kt = 0; kt < 2; kt++) {
            uint4 f = __ldg(bf + (16 + nt * 2 + kt) * 32 + lane);
#pragma unroll
            for (int mt = 0; mt < 2; mt++) {
                mma_f16(cc[mt][nt], &ah[mt][kt * 4], f.x, f.y);
                mma_f16(cc[mt][nt], &ah[mt][kt * 4], f.z, f.w);
                mma_f16(cc[mt][nt], &al[mt][kt * 4], f.x, f.y);
            }
        }
    float* ob = out + (size_t)n * NKP * HW;
#pragma unroll
    for (int mt = 0; mt < 2; mt++) {
        int px0 = pxb + 16 * mt + g, px1 = px0 + 8;
#pragma unroll
        for (int nt = 0; nt < 3; nt++) {
            int o0 = nt * 8 + 2 * tig, o1 = o0 + 1;
            if (o0 < NKP) {
                float bb0 = row[2720 + o0];
                ob[(size_t)o0 * HW + px0] = cc[mt][nt][0] + bb0;
                ob[(size_t)o0 * HW + px1] = cc[mt][nt][2] + bb0;
            }
            if (o1 < NKP) {
                float bb1 = row[2720 + o1];
                ob[(size_t)o1 * HW + px0] = cc[mt][nt][1] + bb1;
                ob[(size_t)o1 * HW + px1] = cc[mt][nt][3] + bb1;
            }
        }
    }
}

// ---------------------------------------------------------------------------
// Kernel C: per (n, kp) argmax over HW, 4 independent accumulator chains,
// first-index tie-break preserved.
// ---------------------------------------------------------------------------
__global__ __launch_bounds__(256) void argmax_kernel(float* __restrict__ out,
                                                     const float* __restrict__ bases_full) {
    int pair = blockIdx.x;
    int k = pair % NKP;
    const float4* lg = (const float4*)(out + (size_t)pair * HW);
    int tid = threadIdx.x;

    float bv0 = -3.4e38f, bv1 = -3.4e38f, bv2 = -3.4e38f, bv3 = -3.4e38f;
    int bi0 = 0, bi1 = 1, bi2 = 2, bi3 = 3;
    for (int q = tid; q < HW / 4; q += 256) {
        float4 v = lg[q];
        int i0 = q * 4;
        if (v.x > bv0) { bv0 = v.x; bi0 = i0; }
        if (v.y > bv1) { bv1 = v.y; bi1 = i0 + 1; }
        if (v.z > bv2) { bv2 = v.z; bi2 = i0 + 2; }
        if (v.w > bv3) { bv3 = v.w; bi3 = i0 + 3; }
    }
    float best = bv0; int bi = bi0;
    if (bv1 > best || (bv1 == best && bi1 < bi)) { best = bv1; bi = bi1; }
    if (bv2 > best || (bv2 == best && bi2 < bi)) { best = bv2; bi = bi2; }
    if (bv3 > best || (bv3 == best && bi3 < bi)) { best = bv3; bi = bi3; }

    __shared__ float sv[256];
    __shared__ int si[256];
    sv[tid] = best;
    si[tid] = bi;
    __syncthreads();
#pragma unroll
    for (int s = 128; s > 0; s >>= 1) {
        if (tid < s) {
            float ov = sv[tid + s]; int oi = si[tid + s];
            if (ov > sv[tid] || (ov == sv[tid] && oi < si[tid])) {
                sv[tid] = ov; si[tid] = oi;
            }
        }
        __syncthreads();
    }
    if (tid == 0) {
        int i = si[0];
        float gx = (float)(i % WDIM) * 8.f + 4.f;
        float gy = (float)(i / WDIM) * 8.f + 4.f;
        float* kp = out + (size_t)NINST * NKP * HW + (size_t)pair * 2;
        kp[0] = bases_full[(size_t)(NB + 2 * k)     * HW + i] + gx;
        kp[1] = bases_full[(size_t)(NB + 2 * k + 1) * HW + i] + gy;
    }
}

// ---------------------------------------------------------------------------
extern "C" void kernel_launch(void* const* d_in, const int* in_sizes, int n_in,
                              void* d_out, int out_size) {
    const float* bases_full = (const float*)d_in[0];
    const float* top_feats  = (const float*)d_in[1];
    const float* locations  = (const float*)d_in[2];
    const float* atten_W    = (const float*)d_in[3];
    const float* atten_b    = (const float*)d_in[4];
    const float* sizes      = (const float*)d_in[5];
    const int*   fpn_levels = (const int*)d_in[6];
    float* out = (float*)d_out;

    gemm_prep<<<GEMM_BLKS + NT16, 128>>>(top_feats, atten_W, bases_full);
    reduce_bfrag<<<NINST + RED_BLKS, 512>>>(atten_b);
    mlp_mma16<<<dim3(GX, NINST), 256>>>(locations, sizes, fpn_levels, out);
    argmax_kernel<<<NINST * NKP, 256>>>(out, bases_full);
}